// round 14
// baseline (speedup 1.0000x reference)
#include <cuda_runtime.h>
#include <cuda_fp16.h>
#include <cuda_bf16.h>
#include <cstdint>

#define TT 8        // timesteps (B*T)
#define FIN 64      // in features
#define HC 128      // H*C
#define NMAX 50016
#define EMAX 460000
#define NEG_SLOPE 0.2f

// bf16 smem tiles, 72-half row pad (144 B) -> conflict-free 32-bit frag LDS
#define XPH 72
#define OFF_XH 0
#define OFF_XL (128 * XPH)
#define OFF_WTH (2 * 128 * XPH)
#define OFF_WTL (3 * 128 * XPH)
#define GEMM_SMEM (4 * 128 * XPH * 2)   // 73728 B

// ---- scratch (device globals; zero-initialized at module load) ----
__device__ int    g_deg[NMAX];     // re-zeroed by k_edge each replay
__device__ int    g_off[NMAX + 1];
__device__ int    g_cur[NMAX];
__device__ int    g_csr_src[EMAX]; // BYTE offsets (node*256)
__device__ int    g_csr_dst[EMAX];
__device__ __nv_bfloat16 g_wth[HC * FIN];  // W^T bf16 hi: [col][k]
__device__ __nv_bfloat16 g_wtl[HC * FIN];  // W^T bf16 lo
__device__ __half g_xl[(size_t)TT * NMAX * HC];   // fp16, ~102 MB
__device__ float  g_as[(size_t)NMAX * TT * 2];    // [n][t][h]
__device__ float  g_ad[(size_t)NMAX * TT * 2];
__device__ float  g_exh[(size_t)TT * 2 * EMAX];   // [t*2+head][csr_pos], ~29 MB
__device__ float  g_den[(size_t)TT * NMAX * 2];   // [t][n][h] softmax denominators

// ---------------- CSR build ----------------
__global__ void k_count(const int* __restrict__ dst, int E, int N) {
    int e = blockIdx.x * blockDim.x + threadIdx.x;
    int total = gridDim.x * blockDim.x;
    // zero denominators for this replay (atomically accumulated in k_edge)
    for (int i = e; i < N * TT * 2; i += total) g_den[i] = 0.f;
    if (e < E) atomicAdd(&g_deg[dst[e]], 1);
}

// scan + (folded) W bf16 hi/lo pre-split, transposed [col][k]
__global__ void k_scan(const float* __restrict__ W, int N) {
    __shared__ int warp_sums[32];
    __shared__ int s_running;
    int tid = threadIdx.x, lane = tid & 31, wid = tid >> 5;

    for (int i = tid; i < HC * FIN; i += 1024) {
        int col = i >> 6, k = i & 63;
        float v = W[k * HC + col];
        __nv_bfloat16 hi = __float2bfloat16_rn(v);
        g_wth[i] = hi;
        g_wtl[i] = __float2bfloat16_rn(v - __bfloat162float(hi));
    }

    if (tid == 0) { s_running = 0; g_off[0] = 0; }
    __syncthreads();
    for (int base = 0; base < N; base += 1024) {
        int i = base + tid;
        int v = (i < N) ? g_deg[i] : 0;
        int x = v;
        #pragma unroll
        for (int o = 1; o < 32; o <<= 1) {
            int y = __shfl_up_sync(0xffffffffu, x, o);
            if (lane >= o) x += y;
        }
        if (lane == 31) warp_sums[wid] = x;
        __syncthreads();
        if (wid == 0) {
            int ws = warp_sums[lane];
            #pragma unroll
            for (int o = 1; o < 32; o <<= 1) {
                int y = __shfl_up_sync(0xffffffffu, ws, o);
                if (lane >= o) ws += y;
            }
            warp_sums[lane] = ws;
        }
        __syncthreads();
        int prefix = s_running + (wid > 0 ? warp_sums[wid - 1] : 0) + x;
        if (i < N) {
            g_off[i + 1] = prefix;
            g_cur[i] = prefix - v;
        }
        __syncthreads();
        if (tid == 0) s_running += warp_sums[31];
        __syncthreads();
    }
}

__global__ void k_fill(const int* __restrict__ src, const int* __restrict__ dst, int E) {
    int e = blockIdx.x * blockDim.x + threadIdx.x;
    if (e < E) {
        int d = dst[e];
        int pos = atomicAdd(&g_cur[d], 1);
        g_csr_src[pos] = src[e] << 8;   // byte offset into 256B xl rows
        g_csr_dst[pos] = d;
    }
}

// ---------------- split-bf16 (3-MMA, k16) tensor-core GEMM + fused scores + fp16 xl ----------------
__device__ __forceinline__ void mma16(float* d, unsigned int a0, unsigned int a1,
                                      unsigned int a2, unsigned int a3,
                                      unsigned int b0, unsigned int b1) {
    asm volatile(
        "mma.sync.aligned.m16n8k16.row.col.f32.bf16.bf16.f32 "
        "{%0,%1,%2,%3},{%4,%5,%6,%7},{%8,%9},{%0,%1,%2,%3};"
        : "+f"(d[0]), "+f"(d[1]), "+f"(d[2]), "+f"(d[3])
        : "r"(a0), "r"(a1), "r"(a2), "r"(a3), "r"(b0), "r"(b1));
}

__device__ __forceinline__ unsigned int packbf2(float a, float b) {
    __nv_bfloat162 p = __floats2bfloat162_rn(a, b);
    return *(unsigned int*)&p;
}

__global__ __launch_bounds__(256, 2) void k_gemm(const float* __restrict__ h,
                                                 const float* __restrict__ att_src,
                                                 const float* __restrict__ att_dst,
                                                 int N) {
    extern __shared__ __nv_bfloat16 smem[];
    __nv_bfloat16* Xh  = smem + OFF_XH;    // [128][72] (node, k)
    __nv_bfloat16* Xl  = smem + OFF_XL;
    __nv_bfloat16* Wth = smem + OFF_WTH;   // [128][72] (col, k)
    __nv_bfloat16* Wtl = smem + OFF_WTL;
    int t = blockIdx.y;
    int n0 = blockIdx.x * 128;
    int tid = threadIdx.x;

    #pragma unroll
    for (int i = 0; i < 4; i++) {
        int idx = tid + i * 256;
        int col = idx >> 3, seg = idx & 7;
        *(uint4*)(Wth + col * XPH + seg * 8) = ((const uint4*)g_wth)[idx];
        *(uint4*)(Wtl + col * XPH + seg * 8) = ((const uint4*)g_wtl)[idx];
    }
    #pragma unroll
    for (int i = 0; i < 8; i++) {
        int idx = tid + i * 256;
        int row = idx >> 4, c4 = idx & 15;
        int n = n0 + row;
        float4 v = make_float4(0.f, 0.f, 0.f, 0.f);
        if (n < N) v = *(const float4*)(h + ((size_t)n * TT + t) * FIN + c4 * 4);
        float hx = __bfloat162float(__float2bfloat16_rn(v.x));
        float hy = __bfloat162float(__float2bfloat16_rn(v.y));
        float hz = __bfloat162float(__float2bfloat16_rn(v.z));
        float hw = __bfloat162float(__float2bfloat16_rn(v.w));
        uint2 hi2 = make_uint2(packbf2(v.x, v.y), packbf2(v.z, v.w));
        uint2 lo2 = make_uint2(packbf2(v.x - hx, v.y - hy), packbf2(v.z - hz, v.w - hw));
        *(uint2*)(Xh + row * XPH + c4 * 4) = hi2;
        *(uint2*)(Xl + row * XPH + c4 * 4) = lo2;
    }
    __syncthreads();

    int wid = tid >> 5, lane = tid & 31;
    int R = (wid & 3) * 32;
    int CB = (wid >> 2) * 64;
    int p = lane >> 2, q = lane & 3;

    float acc[2][8][4];
    #pragma unroll
    for (int rt = 0; rt < 2; rt++)
        #pragma unroll
        for (int nt = 0; nt < 8; nt++)
            #pragma unroll
            for (int c = 0; c < 4; c++) acc[rt][nt][c] = 0.f;

    #pragma unroll
    for (int kt = 0; kt < 4; kt++) {        // k16 steps
        int k0 = kt * 16 + q * 2;
        unsigned int ah[2][4], al[2][4];
        #pragma unroll
        for (int rt = 0; rt < 2; rt++) {
            int r0 = R + rt * 16 + p;
            ah[rt][0] = *(unsigned int*)(Xh + r0 * XPH + k0);
            ah[rt][1] = *(unsigned int*)(Xh + (r0 + 8) * XPH + k0);
            ah[rt][2] = *(unsigned int*)(Xh + r0 * XPH + k0 + 8);
            ah[rt][3] = *(unsigned int*)(Xh + (r0 + 8) * XPH + k0 + 8);
            al[rt][0] = *(unsigned int*)(Xl + r0 * XPH + k0);
            al[rt][1] = *(unsigned int*)(Xl + (r0 + 8) * XPH + k0);
            al[rt][2] = *(unsigned int*)(Xl + r0 * XPH + k0 + 8);
            al[rt][3] = *(unsigned int*)(Xl + (r0 + 8) * XPH + k0 + 8);
        }
        #pragma unroll
        for (int nt = 0; nt < 8; nt++) {
            int col = CB + nt * 8 + p;
            unsigned int bh0 = *(unsigned int*)(Wth + col * XPH + k0);
            unsigned int bh1 = *(unsigned int*)(Wth + col * XPH + k0 + 8);
            unsigned int bl0 = *(unsigned int*)(Wtl + col * XPH + k0);
            unsigned int bl1 = *(unsigned int*)(Wtl + col * XPH + k0 + 8);
            #pragma unroll
            for (int rt = 0; rt < 2; rt++) {
                mma16(acc[rt][nt], ah[rt][0], ah[rt][1], ah[rt][2], ah[rt][3], bh0, bh1);
                mma16(acc[rt][nt], ah[rt][0], ah[rt][1], ah[rt][2], ah[rt][3], bl0, bl1);
                mma16(acc[rt][nt], al[rt][0], al[rt][1], al[rt][2], al[rt][3], bh0, bh1);
            }
        }
    }

    // ---- fused attention scores ----
    int head = wid >> 2;
    float sa[16], da[16];
    #pragma unroll
    for (int nt = 0; nt < 8; nt++)
        #pragma unroll
        for (int j = 0; j < 2; j++) {
            int col = CB + nt * 8 + q * 2 + j;
            sa[nt * 2 + j] = __ldg(att_src + col);
            da[nt * 2 + j] = __ldg(att_dst + col);
        }
    #pragma unroll
    for (int rt = 0; rt < 2; rt++)
        #pragma unroll
        for (int half = 0; half < 2; half++) {
            float ps = 0.f, pd = 0.f;
            #pragma unroll
            for (int nt = 0; nt < 8; nt++) {
                ps = fmaf(acc[rt][nt][half * 2 + 0], sa[nt * 2 + 0], ps);
                ps = fmaf(acc[rt][nt][half * 2 + 1], sa[nt * 2 + 1], ps);
                pd = fmaf(acc[rt][nt][half * 2 + 0], da[nt * 2 + 0], pd);
                pd = fmaf(acc[rt][nt][half * 2 + 1], da[nt * 2 + 1], pd);
            }
            ps += __shfl_xor_sync(0xffffffffu, ps, 1);
            ps += __shfl_xor_sync(0xffffffffu, ps, 2);
            pd += __shfl_xor_sync(0xffffffffu, pd, 1);
            pd += __shfl_xor_sync(0xffffffffu, pd, 2);
            if (q == 0) {
                int n = n0 + R + rt * 16 + half * 8 + p;
                if (n < N) {
                    g_as[((size_t)n * TT + t) * 2 + head] = ps;
                    g_ad[((size_t)n * TT + t) * 2 + head] = pd;
                }
            }
        }

    // ---- stage fp16 tile (128x128 = 32 KB), then coalesced dump ----
    __syncthreads();
    __half* XsH = (__half*)smem;
    #pragma unroll
    for (int rt = 0; rt < 2; rt++)
        #pragma unroll
        for (int nt = 0; nt < 8; nt++)
            #pragma unroll
            for (int half = 0; half < 2; half++) {
                int row = R + rt * 16 + half * 8 + p;
                int col = CB + nt * 8 + q * 2;
                __half2 hv = __floats2half2_rn(acc[rt][nt][half * 2 + 0],
                                               acc[rt][nt][half * 2 + 1]);
                *(__half2*)(XsH + row * HC + col) = hv;
            }
    __syncthreads();
    {
        __half* dstp = g_xl + ((size_t)t * N + n0) * HC;
        const uint4* s4 = (const uint4*)XsH;
        #pragma unroll
        for (int i = 0; i < 8; i++) {
            int idx = tid + i * 256;
            int n = n0 + (idx >> 4);
            if (n < N) ((uint4*)dstp)[idx] = s4[idx];
        }
    }
}

// ---------------- per (t, csr-pos) edge exp weights + denominator atomics ----------------
__global__ __launch_bounds__(256) void k_edge(int E, int N) {
    int pos = blockIdx.x * blockDim.x + threadIdx.x;
    int t = blockIdx.y;
    if (t == 0 && pos < N) g_deg[pos] = 0;   // re-arm for next graph replay
    if (pos >= E) return;
    int s = g_csr_src[pos] >> 8;   // stored as byte offset
    int d = g_csr_dst[pos];
    float2 a = *(const float2*)(g_as + ((size_t)s * TT + t) * 2);
    float2 b = *(const float2*)(g_ad + ((size_t)d * TT + t) * 2);
    float x0 = a.x + b.x, x1 = a.y + b.y;
    x0 = x0 > 0.f ? x0 : NEG_SLOPE * x0;
    x1 = x1 > 0.f ? x1 : NEG_SLOPE * x1;
    // scores bounded (|x| << 80): exp without max-subtraction is overflow-safe
    float e0 = __expf(x0), e1 = __expf(x1);
    g_exh[((size_t)(t * 2 + 0)) * E + pos] = e0;
    g_exh[((size_t)(t * 2 + 1)) * E + pos] = e1;
    atomicAdd(&g_den[((size_t)t * N + d) * 2 + 0], e0);
    atomicAdd(&g_den[((size_t)t * N + d) * 2 + 1], e1);
}

// ---------------- aggregation: one warp per (t,n), lean loop ----------------
// Per edge: LDG byte-offset + LDG head-split ex + LDG.64 gather + 2 cvt + 4 FMA.
__global__ __launch_bounds__(256) void k_agg(const float* __restrict__ bias,
                                             float* __restrict__ out, int N, int E) {
    int gw = (blockIdx.x * blockDim.x + threadIdx.x) >> 5;
    int lane = threadIdx.x & 31;
    if (gw >= TT * N) return;
    int t = gw / N, n = gw - t * N;

    int head = lane >> 4;
    const char* xlb = (const char*)(g_xl + (size_t)t * N * HC) + lane * 8;
    const float* exb = g_exh + ((size_t)(t * 2 + head)) * E;
    int s0 = g_off[n], s1 = g_off[n + 1];

    float4 acc = make_float4(0.f, 0.f, 0.f, 0.f);
    #pragma unroll 2
    for (int e = s0; e < s1; e++) {
        int off = __ldg(&g_csr_src[e]);           // byte offset, uniform across warp
        float ex = __ldg(&exb[e]);
        uint2 raw = *(const uint2*)(xlb + off);
        float2 v01 = __half22float2(*(__half2*)&raw.x);
        float2 v23 = __half22float2(*(__half2*)&raw.y);
        acc.x = fmaf(ex, v01.x, acc.x);
        acc.y = fmaf(ex, v01.y, acc.y);
        acc.z = fmaf(ex, v23.x, acc.z);
        acc.w = fmaf(ex, v23.y, acc.w);
    }
    float den = __ldg(&g_den[((size_t)t * N + n) * 2 + head]);
    float inv = 1.f / den;
    acc.x *= inv; acc.y *= inv; acc.z *= inv; acc.w *= inv;

    float px = __shfl_down_sync(0xffffffffu, acc.x, 16);
    float py = __shfl_down_sync(0xffffffffu, acc.y, 16);
    float pz = __shfl_down_sync(0xffffffffu, acc.z, 16);
    float pw = __shfl_down_sync(0xffffffffu, acc.w, 16);
    if (head == 0) {
        float4 b4 = *(const float4*)(bias + lane * 4);
        float4 o4;
        o4.x = 0.5f * (acc.x + px) + b4.x;
        o4.y = 0.5f * (acc.y + py) + b4.y;
        o4.z = 0.5f * (acc.z + pz) + b4.z;
        o4.w = 0.5f * (acc.w + pw) + b4.w;
        o4.x = o4.x > 0.f ? o4.x : (__expf(o4.x) - 1.f);
        o4.y = o4.y > 0.f ? o4.y : (__expf(o4.y) - 1.f);
        o4.z = o4.z > 0.f ? o4.z : (__expf(o4.z) - 1.f);
        o4.w = o4.w > 0.f ? o4.w : (__expf(o4.w) - 1.f);
        *(float4*)(out + ((size_t)n * TT + t) * 64 + lane * 4) = o4;
    }
}

extern "C" void kernel_launch(void* const* d_in, const int* in_sizes, int n_in,
                              void* d_out, int out_size) {
    const float* h       = (const float*)d_in[0];
    const int*   src     = (const int*)d_in[1];
    const int*   dst     = (const int*)d_in[2];
    const float* W       = (const float*)d_in[3];
    const float* att_src = (const float*)d_in[4];
    const float* att_dst = (const float*)d_in[5];
    const float* bias    = (const float*)d_in[6];
    float* out = (float*)d_out;

    int E = in_sizes[1];
    int N = in_sizes[0] / (TT * FIN);
    if (N > NMAX) N = NMAX;
    if (E > EMAX) E = EMAX;

    cudaFuncSetAttribute(k_gemm, cudaFuncAttributeMaxDynamicSharedMemorySize, GEMM_SMEM);

    // CSR build + W pre-split (g_deg zero: module-load init, k_edge re-arms)
    k_count<<<(E + 255) / 256, 256>>>(dst, E, N);                   // launch 1 (+ den zero)
    k_scan<<<1, 1024>>>(W, N);                                      // launch 2 (+ W split)
    k_fill<<<(E + 255) / 256, 256>>>(src, dst, E);                  // launch 3

    // split-bf16 tensor-core GEMM + fused scores (launch 4 -> ncu capture slot)
    dim3 ggrid((N + 127) / 128, TT);
    k_gemm<<<ggrid, 256, GEMM_SMEM>>>(h, att_src, att_dst, N);      // launch 4

    // per-edge exp weights + denominators + g_deg re-zero
    dim3 egrid((E + 255) / 256, TT);
    k_edge<<<egrid, 256>>>(E, N);                                   // launch 5

    // aggregation: one warp per (t, node)
    int total_warps = TT * N;
    int ablocks = (total_warps * 32 + 255) / 256;
    k_agg<<<ablocks, 256>>>(bias, out, N, E);                       // launch 6
}

// round 15
// speedup vs baseline: 1.0958x; 1.0958x over previous
#include <cuda_runtime.h>
#include <cuda_fp16.h>
#include <cuda_bf16.h>
#include <cstdint>

#define TT 8        // timesteps (B*T)
#define FIN 64      // in features
#define HC 128      // H*C
#define NMAX 50016
#define EMAX 460000
#define NEG_SLOPE 0.2f

// bf16 smem tiles, 72-half row pad (144 B) -> conflict-free 32-bit frag LDS
#define XPH 72
#define OFF_XH 0
#define OFF_XL (128 * XPH)
#define OFF_WTH (2 * 128 * XPH)
#define OFF_WTL (3 * 128 * XPH)
#define GEMM_SMEM (4 * 128 * XPH * 2)   // 73728 B

// ---- scratch (device globals; zero-initialized at module load) ----
__device__ int    g_deg[NMAX];     // re-zeroed by k_edge each replay
__device__ int    g_off[NMAX + 1];
__device__ int    g_cur[NMAX];
__device__ int    g_csr_src[EMAX]; // BYTE offsets (node*256)
__device__ int    g_csr_dst[EMAX];
__device__ __nv_bfloat16 g_wth[HC * FIN];  // W^T bf16 hi: [col][k]
__device__ __nv_bfloat16 g_wtl[HC * FIN];  // W^T bf16 lo
__device__ __half g_xl[(size_t)TT * NMAX * HC];   // fp16, ~102 MB
__device__ float  g_as[(size_t)NMAX * TT * 2];    // [n][t][h]
__device__ float  g_ad[(size_t)NMAX * TT * 2];
__device__ float2 g_ex[(size_t)TT * EMAX];        // [t][csr_pos], ~29 MB

// ---------------- CSR build ----------------
__global__ void k_count(const int* __restrict__ dst, int E) {
    int e = blockIdx.x * blockDim.x + threadIdx.x;
    if (e < E) atomicAdd(&g_deg[dst[e]], 1);
}

// scan + (folded) W bf16 hi/lo pre-split, transposed [col][k]
__global__ void k_scan(const float* __restrict__ W, int N) {
    __shared__ int warp_sums[32];
    __shared__ int s_running;
    int tid = threadIdx.x, lane = tid & 31, wid = tid >> 5;

    for (int i = tid; i < HC * FIN; i += 1024) {
        int col = i >> 6, k = i & 63;
        float v = W[k * HC + col];
        __nv_bfloat16 hi = __float2bfloat16_rn(v);
        g_wth[i] = hi;
        g_wtl[i] = __float2bfloat16_rn(v - __bfloat162float(hi));
    }

    if (tid == 0) { s_running = 0; g_off[0] = 0; }
    __syncthreads();
    for (int base = 0; base < N; base += 1024) {
        int i = base + tid;
        int v = (i < N) ? g_deg[i] : 0;
        int x = v;
        #pragma unroll
        for (int o = 1; o < 32; o <<= 1) {
            int y = __shfl_up_sync(0xffffffffu, x, o);
            if (lane >= o) x += y;
        }
        if (lane == 31) warp_sums[wid] = x;
        __syncthreads();
        if (wid == 0) {
            int ws = warp_sums[lane];
            #pragma unroll
            for (int o = 1; o < 32; o <<= 1) {
                int y = __shfl_up_sync(0xffffffffu, ws, o);
                if (lane >= o) ws += y;
            }
            warp_sums[lane] = ws;
        }
        __syncthreads();
        int prefix = s_running + (wid > 0 ? warp_sums[wid - 1] : 0) + x;
        if (i < N) {
            g_off[i + 1] = prefix;
            g_cur[i] = prefix - v;
        }
        __syncthreads();
        if (tid == 0) s_running += warp_sums[31];
        __syncthreads();
    }
}

__global__ void k_fill(const int* __restrict__ src, const int* __restrict__ dst, int E) {
    int e = blockIdx.x * blockDim.x + threadIdx.x;
    if (e < E) {
        int d = dst[e];
        int pos = atomicAdd(&g_cur[d], 1);
        g_csr_src[pos] = src[e] << 8;   // byte offset into 256B xl rows
        g_csr_dst[pos] = d;
    }
}

// ---------------- split-bf16 (3-MMA, k16) tensor-core GEMM + fused scores + fp16 xl ----------------
__device__ __forceinline__ void mma16(float* d, unsigned int a0, unsigned int a1,
                                      unsigned int a2, unsigned int a3,
                                      unsigned int b0, unsigned int b1) {
    asm volatile(
        "mma.sync.aligned.m16n8k16.row.col.f32.bf16.bf16.f32 "
        "{%0,%1,%2,%3},{%4,%5,%6,%7},{%8,%9},{%0,%1,%2,%3};"
        : "+f"(d[0]), "+f"(d[1]), "+f"(d[2]), "+f"(d[3])
        : "r"(a0), "r"(a1), "r"(a2), "r"(a3), "r"(b0), "r"(b1));
}

__device__ __forceinline__ unsigned int packbf2(float a, float b) {
    __nv_bfloat162 p = __floats2bfloat162_rn(a, b);
    return *(unsigned int*)&p;
}

__global__ __launch_bounds__(256, 2) void k_gemm(const float* __restrict__ h,
                                                 const float* __restrict__ att_src,
                                                 const float* __restrict__ att_dst,
                                                 int N) {
    extern __shared__ __nv_bfloat16 smem[];
    __nv_bfloat16* Xh  = smem + OFF_XH;    // [128][72] (node, k)
    __nv_bfloat16* Xl  = smem + OFF_XL;
    __nv_bfloat16* Wth = smem + OFF_WTH;   // [128][72] (col, k)
    __nv_bfloat16* Wtl = smem + OFF_WTL;
    int t = blockIdx.y;
    int n0 = blockIdx.x * 128;
    int tid = threadIdx.x;

    #pragma unroll
    for (int i = 0; i < 4; i++) {
        int idx = tid + i * 256;
        int col = idx >> 3, seg = idx & 7;
        *(uint4*)(Wth + col * XPH + seg * 8) = ((const uint4*)g_wth)[idx];
        *(uint4*)(Wtl + col * XPH + seg * 8) = ((const uint4*)g_wtl)[idx];
    }
    #pragma unroll
    for (int i = 0; i < 8; i++) {
        int idx = tid + i * 256;
        int row = idx >> 4, c4 = idx & 15;
        int n = n0 + row;
        float4 v = make_float4(0.f, 0.f, 0.f, 0.f);
        if (n < N) v = *(const float4*)(h + ((size_t)n * TT + t) * FIN + c4 * 4);
        float hx = __bfloat162float(__float2bfloat16_rn(v.x));
        float hy = __bfloat162float(__float2bfloat16_rn(v.y));
        float hz = __bfloat162float(__float2bfloat16_rn(v.z));
        float hw = __bfloat162float(__float2bfloat16_rn(v.w));
        uint2 hi2 = make_uint2(packbf2(v.x, v.y), packbf2(v.z, v.w));
        uint2 lo2 = make_uint2(packbf2(v.x - hx, v.y - hy), packbf2(v.z - hz, v.w - hw));
        *(uint2*)(Xh + row * XPH + c4 * 4) = hi2;
        *(uint2*)(Xl + row * XPH + c4 * 4) = lo2;
    }
    __syncthreads();

    int wid = tid >> 5, lane = tid & 31;
    int R = (wid & 3) * 32;
    int CB = (wid >> 2) * 64;
    int p = lane >> 2, q = lane & 3;

    float acc[2][8][4];
    #pragma unroll
    for (int rt = 0; rt < 2; rt++)
        #pragma unroll
        for (int nt = 0; nt < 8; nt++)
            #pragma unroll
            for (int c = 0; c < 4; c++) acc[rt][nt][c] = 0.f;

    #pragma unroll
    for (int kt = 0; kt < 4; kt++) {        // k16 steps
        int k0 = kt * 16 + q * 2;
        unsigned int ah[2][4], al[2][4];
        #pragma unroll
        for (int rt = 0; rt < 2; rt++) {
            int r0 = R + rt * 16 + p;
            ah[rt][0] = *(unsigned int*)(Xh + r0 * XPH + k0);
            ah[rt][1] = *(unsigned int*)(Xh + (r0 + 8) * XPH + k0);
            ah[rt][2] = *(unsigned int*)(Xh + r0 * XPH + k0 + 8);
            ah[rt][3] = *(unsigned int*)(Xh + (r0 + 8) * XPH + k0 + 8);
            al[rt][0] = *(unsigned int*)(Xl + r0 * XPH + k0);
            al[rt][1] = *(unsigned int*)(Xl + (r0 + 8) * XPH + k0);
            al[rt][2] = *(unsigned int*)(Xl + r0 * XPH + k0 + 8);
            al[rt][3] = *(unsigned int*)(Xl + (r0 + 8) * XPH + k0 + 8);
        }
        #pragma unroll
        for (int nt = 0; nt < 8; nt++) {
            int col = CB + nt * 8 + p;
            unsigned int bh0 = *(unsigned int*)(Wth + col * XPH + k0);
            unsigned int bh1 = *(unsigned int*)(Wth + col * XPH + k0 + 8);
            unsigned int bl0 = *(unsigned int*)(Wtl + col * XPH + k0);
            unsigned int bl1 = *(unsigned int*)(Wtl + col * XPH + k0 + 8);
            #pragma unroll
            for (int rt = 0; rt < 2; rt++) {
                mma16(acc[rt][nt], ah[rt][0], ah[rt][1], ah[rt][2], ah[rt][3], bh0, bh1);
                mma16(acc[rt][nt], ah[rt][0], ah[rt][1], ah[rt][2], ah[rt][3], bl0, bl1);
                mma16(acc[rt][nt], al[rt][0], al[rt][1], al[rt][2], al[rt][3], bh0, bh1);
            }
        }
    }

    // ---- fused attention scores ----
    int head = wid >> 2;
    float sa[16], da[16];
    #pragma unroll
    for (int nt = 0; nt < 8; nt++)
        #pragma unroll
        for (int j = 0; j < 2; j++) {
            int col = CB + nt * 8 + q * 2 + j;
            sa[nt * 2 + j] = __ldg(att_src + col);
            da[nt * 2 + j] = __ldg(att_dst + col);
        }
    #pragma unroll
    for (int rt = 0; rt < 2; rt++)
        #pragma unroll
        for (int half = 0; half < 2; half++) {
            float ps = 0.f, pd = 0.f;
            #pragma unroll
            for (int nt = 0; nt < 8; nt++) {
                ps = fmaf(acc[rt][nt][half * 2 + 0], sa[nt * 2 + 0], ps);
                ps = fmaf(acc[rt][nt][half * 2 + 1], sa[nt * 2 + 1], ps);
                pd = fmaf(acc[rt][nt][half * 2 + 0], da[nt * 2 + 0], pd);
                pd = fmaf(acc[rt][nt][half * 2 + 1], da[nt * 2 + 1], pd);
            }
            ps += __shfl_xor_sync(0xffffffffu, ps, 1);
            ps += __shfl_xor_sync(0xffffffffu, ps, 2);
            pd += __shfl_xor_sync(0xffffffffu, pd, 1);
            pd += __shfl_xor_sync(0xffffffffu, pd, 2);
            if (q == 0) {
                int n = n0 + R + rt * 16 + half * 8 + p;
                if (n < N) {
                    g_as[((size_t)n * TT + t) * 2 + head] = ps;
                    g_ad[((size_t)n * TT + t) * 2 + head] = pd;
                }
            }
        }

    // ---- stage fp16 tile (128x128 = 32 KB), then coalesced dump ----
    __syncthreads();
    __half* XsH = (__half*)smem;
    #pragma unroll
    for (int rt = 0; rt < 2; rt++)
        #pragma unroll
        for (int nt = 0; nt < 8; nt++)
            #pragma unroll
            for (int half = 0; half < 2; half++) {
                int row = R + rt * 16 + half * 8 + p;
                int col = CB + nt * 8 + q * 2;
                __half2 hv = __floats2half2_rn(acc[rt][nt][half * 2 + 0],
                                               acc[rt][nt][half * 2 + 1]);
                *(__half2*)(XsH + row * HC + col) = hv;
            }
    __syncthreads();
    {
        __half* dstp = g_xl + ((size_t)t * N + n0) * HC;
        const uint4* s4 = (const uint4*)XsH;
        #pragma unroll
        for (int i = 0; i < 8; i++) {
            int idx = tid + i * 256;
            int n = n0 + (idx >> 4);
            if (n < N) ((uint4*)dstp)[idx] = s4[idx];
        }
    }
}

// ---------------- SINGLE-PASS per-edge exp weights: one thread per csr-pos, t-loop inside ----------------
// Reads indices once, node scores as contiguous float4s, writes g_ex coalesced per slab.
__global__ __launch_bounds__(256) void k_edge(int E, int N) {
    int pos = blockIdx.x * blockDim.x + threadIdx.x;
    if (pos < N) g_deg[pos] = 0;    // re-arm for next graph replay
    if (pos >= E) return;
    int s = g_csr_src[pos] >> 8;    // stored as byte offset
    int d = g_csr_dst[pos];

    // all-timestep scores for src (a_s) and dst (a_d): 16 floats each = 4 float4
    float4 av[4], bv[4];
    const float4* ap = (const float4*)(g_as + (size_t)s * TT * 2);
    const float4* bp = (const float4*)(g_ad + (size_t)d * TT * 2);
    #pragma unroll
    for (int i = 0; i < 4; i++) { av[i] = __ldg(&ap[i]); bv[i] = __ldg(&bp[i]); }

    const float* af = (const float*)av;
    const float* bf = (const float*)bv;
    #pragma unroll
    for (int t = 0; t < TT; t++) {
        float x0 = af[t * 2 + 0] + bf[t * 2 + 0];
        float x1 = af[t * 2 + 1] + bf[t * 2 + 1];
        x0 = x0 > 0.f ? x0 : NEG_SLOPE * x0;
        x1 = x1 > 0.f ? x1 : NEG_SLOPE * x1;
        // scores bounded (|x| << 80): exp without max-subtraction is overflow-safe
        g_ex[(size_t)t * E + pos] = make_float2(__expf(x0), __expf(x1));
    }
}

// ---------------- aggregation (R13 structure, byte-offset indices) ----------------
__global__ __launch_bounds__(256) void k_agg(const float* __restrict__ bias,
                                             float* __restrict__ out, int N, int E) {
    int gw = (blockIdx.x * blockDim.x + threadIdx.x) >> 5;
    int lane = threadIdx.x & 31;
    if (gw >= TT * N) return;
    int t = gw / N, n = gw - t * N;

    const char* xlb = (const char*)(g_xl + (size_t)t * N * HC) + lane * 8;
    const float2* exb = g_ex + (size_t)t * E;
    int s0 = g_off[n], s1 = g_off[n + 1];
    bool hh0 = lane < 16;

    float4 acc = make_float4(0.f, 0.f, 0.f, 0.f);
    float den = 0.f;
    for (int e = s0; e < s1; e++) {
        int off = __ldg(&g_csr_src[e]);           // byte offset, uniform across warp
        float2 exv = __ldg(&exb[e]);
        float ex = hh0 ? exv.x : exv.y;
        den += ex;
        uint2 raw = *(const uint2*)(xlb + off);
        float2 v01 = __half22float2(*(__half2*)&raw.x);
        float2 v23 = __half22float2(*(__half2*)&raw.y);
        acc.x = fmaf(ex, v01.x, acc.x);
        acc.y = fmaf(ex, v01.y, acc.y);
        acc.z = fmaf(ex, v23.x, acc.z);
        acc.w = fmaf(ex, v23.y, acc.w);
    }
    float inv = 1.f / den;
    acc.x *= inv; acc.y *= inv; acc.z *= inv; acc.w *= inv;

    float px = __shfl_down_sync(0xffffffffu, acc.x, 16);
    float py = __shfl_down_sync(0xffffffffu, acc.y, 16);
    float pz = __shfl_down_sync(0xffffffffu, acc.z, 16);
    float pw = __shfl_down_sync(0xffffffffu, acc.w, 16);
    if (hh0) {
        float4 b4 = *(const float4*)(bias + lane * 4);
        float4 o4;
        o4.x = 0.5f * (acc.x + px) + b4.x;
        o4.y = 0.5f * (acc.y + py) + b4.y;
        o4.z = 0.5f * (acc.z + pz) + b4.z;
        o4.w = 0.5f * (acc.w + pw) + b4.w;
        o4.x = o4.x > 0.f ? o4.x : (__expf(o4.x) - 1.f);
        o4.y = o4.y > 0.f ? o4.y : (__expf(o4.y) - 1.f);
        o4.z = o4.z > 0.f ? o4.z : (__expf(o4.z) - 1.f);
        o4.w = o4.w > 0.f ? o4.w : (__expf(o4.w) - 1.f);
        *(float4*)(out + ((size_t)n * TT + t) * 64 + lane * 4) = o4;
    }
}

extern "C" void kernel_launch(void* const* d_in, const int* in_sizes, int n_in,
                              void* d_out, int out_size) {
    const float* h       = (const float*)d_in[0];
    const int*   src     = (const int*)d_in[1];
    const int*   dst     = (const int*)d_in[2];
    const float* W       = (const float*)d_in[3];
    const float* att_src = (const float*)d_in[4];
    const float* att_dst = (const float*)d_in[5];
    const float* bias    = (const float*)d_in[6];
    float* out = (float*)d_out;

    int E = in_sizes[1];
    int N = in_sizes[0] / (TT * FIN);
    if (N > NMAX) N = NMAX;
    if (E > EMAX) E = EMAX;

    cudaFuncSetAttribute(k_gemm, cudaFuncAttributeMaxDynamicSharedMemorySize, GEMM_SMEM);

    // CSR build + W pre-split (g_deg zero: module-load init, k_edge re-arms)
    k_count<<<(E + 255) / 256, 256>>>(dst, E);                      // launch 1
    k_scan<<<1, 1024>>>(W, N);                                      // launch 2 (+ W split)
    k_fill<<<(E + 255) / 256, 256>>>(src, dst, E);                  // launch 3

    // split-bf16 tensor-core GEMM + fused scores (launch 4 -> ncu capture slot)
    dim3 ggrid((N + 127) / 128, TT);
    k_gemm<<<ggrid, 256, GEMM_SMEM>>>(h, att_src, att_dst, N);      // launch 4

    // single-pass per-edge exp weights (all timesteps) + g_deg re-zero
    k_edge<<<(E + 255) / 256, 256>>>(E, N);                         // launch 5

    // aggregation: one warp per (t, node)
    int total_warps = TT * N;
    int ablocks = (total_warps * 32 + 255) / 256;
    k_agg<<<ablocks, 256>>>(bias, out, N, E);                       // launch 6
}